// round 11
// baseline (speedup 1.0000x reference)
#include <cuda_runtime.h>
#include <cuda_bf16.h>
#include <math.h>
#include <stdint.h>

#define BB 8
#define QQL 1024
#define KKL 1024
#define DDIM 1024
#define NH 16
#define HDIM 64
#define FFD 4096
#define MROWS (BB*QQL)   /* 8192 */
#define GS 40            /* gemm3/av smem row stride (bf16 elems) */
#define APLANE (256*GS)
#define BPLANE (128*GS)

// ---------------- scratch (device globals) ----------------
__device__ __nv_bfloat16 g_xn_h[(size_t)2 * MROWS * DDIM],  g_xn_l[(size_t)2 * MROWS * DDIM];
__device__ __nv_bfloat16 g_qkp_h[(size_t)2 * MROWS * DDIM], g_qkp_l[(size_t)2 * MROWS * DDIM];
__device__ __nv_bfloat16 g_lnf_h[(size_t)MROWS * DDIM], g_lnf_l[(size_t)MROWS * DDIM];
__device__ __nv_bfloat16 g_vt_h[(size_t)MROWS * DDIM];
__device__ __nv_bfloat16 g_ao_h[(size_t)MROWS * DDIM];
__device__ __nv_bfloat16 g_hh[(size_t)MROWS * FFD],     g_hl[(size_t)MROWS * FFD];
__device__ __nv_bfloat16 g_w_h[(size_t)12 * 1024 * 1024], g_w_l[(size_t)12 * 1024 * 1024];
__device__ __nv_bfloat16 g_attn_h[(size_t)BB * NH * QQL * KKL];   // 256 MB
__device__ float g_v[(size_t)MROWS * DDIM];
__device__ float g_x[(size_t)MROWS * DDIM];
__device__ int   g_mask_flag;

// ---------------- helpers ----------------
__device__ __forceinline__ uint32_t smem_u32(const void* p) {
    return (uint32_t)__cvta_generic_to_shared(p);
}
__device__ __forceinline__ void cpa16(uint32_t dst, const void* src) {
    asm volatile("cp.async.cg.shared.global [%0], [%1], 16;\n" :: "r"(dst), "l"(src));
}
__device__ __forceinline__ void cpa_commit() { asm volatile("cp.async.commit_group;\n"); }
__device__ __forceinline__ void cpa_wait0() { asm volatile("cp.async.wait_group 0;\n"); }
__device__ __forceinline__ void cpa_wait1() { asm volatile("cp.async.wait_group 1;\n"); }

__device__ __forceinline__ void mma_bf16(float* c, const uint32_t* a, uint32_t b0, uint32_t b1) {
    asm volatile(
        "mma.sync.aligned.m16n8k16.row.col.f32.bf16.bf16.f32 "
        "{%0,%1,%2,%3}, {%4,%5,%6,%7}, {%8,%9}, {%0,%1,%2,%3};\n"
        : "+f"(c[0]), "+f"(c[1]), "+f"(c[2]), "+f"(c[3])
        : "r"(a[0]), "r"(a[1]), "r"(a[2]), "r"(a[3]), "r"(b0), "r"(b1));
}
__device__ __forceinline__ void ldsm_x4(uint32_t* r, uint32_t addr) {
    asm volatile("ldmatrix.sync.aligned.m8n8.x4.shared.b16 {%0,%1,%2,%3}, [%4];\n"
                 : "=r"(r[0]), "=r"(r[1]), "=r"(r[2]), "=r"(r[3]) : "r"(addr));
}
__device__ __forceinline__ float gelu_exact(float v) {
    return 0.5f * v * (1.0f + erff(v * 0.70710678118654752f));
}

// ---------------- mask dtype sniffing ----------------
__global__ void detect_mask_kernel(const unsigned char* __restrict__ m) {
    __shared__ int c1, c2, c3;
    if (threadIdx.x == 0) { c1 = 0; c2 = 0; c3 = 0; }
    __syncthreads();
    for (int i = threadIdx.x; i < BB * KKL; i += blockDim.x) {
        unsigned char v = m[i];
        if (v) {
            int p = i & 3;
            if (p == 1) atomicAdd(&c1, 1);
            else if (p == 2) atomicAdd(&c2, 1);
            else if (p == 3) atomicAdd(&c3, 1);
        }
    }
    __syncthreads();
    if (threadIdx.x == 0) {
        int f;
        if (c1 == 0 && c2 == 0 && c3 == 0) f = 0;  // int32
        else if (c1 == 0) f = 2;                   // float32
        else f = 1;                                // uint8
        g_mask_flag = f;
    }
}

__device__ __forceinline__ bool mask_valid(const void* m, int idx, int flag) {
    if (flag == 1) return ((const unsigned char*)m)[idx] != 0;
    if (flag == 2) return ((const float*)m)[idx] != 0.0f;
    return ((const int*)m)[idx] != 0;
}

// ---------------- split fp32 -> bf16 hi/lo ----------------
__global__ void __launch_bounds__(256) split_kernel(
    const float* __restrict__ x, __nv_bfloat16* __restrict__ hi,
    __nv_bfloat16* __restrict__ lo, size_t n)
{
    size_t i = ((size_t)blockIdx.x * 256 + threadIdx.x) * 4;
    if (i >= n) return;
    float4 v = *(const float4*)(x + i);
    __nv_bfloat16 h0 = __float2bfloat16_rn(v.x);
    __nv_bfloat16 h1 = __float2bfloat16_rn(v.y);
    __nv_bfloat16 h2 = __float2bfloat16_rn(v.z);
    __nv_bfloat16 h3 = __float2bfloat16_rn(v.w);
    __nv_bfloat162* hp = (__nv_bfloat162*)(hi + i);
    hp[0] = __nv_bfloat162(h0, h1);
    hp[1] = __nv_bfloat162(h2, h3);
    __nv_bfloat162* lp = (__nv_bfloat162*)(lo + i);
    lp[0] = __nv_bfloat162(__float2bfloat16_rn(v.x - __bfloat162float(h0)),
                           __float2bfloat16_rn(v.y - __bfloat162float(h1)));
    lp[1] = __nv_bfloat162(__float2bfloat16_rn(v.z - __bfloat162float(h2)),
                           __float2bfloat16_rn(v.w - __bfloat162float(h3)));
}

// ---------------- layernorm -> split bf16 hi/lo ----------------
__global__ void __launch_bounds__(256) ln_split_kernel(
    const float* __restrict__ x, const float* __restrict__ w,
    const float* __restrict__ b, __nv_bfloat16* __restrict__ hi,
    __nv_bfloat16* __restrict__ lo)
{
    int row = blockIdx.x;
    const float* xr = x + (size_t)row * DDIM;
    float sum = 0.f, sumsq = 0.f;
    for (int i = threadIdx.x; i < DDIM; i += blockDim.x) {
        float v = xr[i]; sum += v; sumsq += v * v;
    }
    __shared__ float s1[32], s2[32];
    for (int o = 16; o; o >>= 1) {
        sum   += __shfl_down_sync(0xffffffffu, sum, o);
        sumsq += __shfl_down_sync(0xffffffffu, sumsq, o);
    }
    int lane = threadIdx.x & 31, wid = threadIdx.x >> 5;
    if (lane == 0) { s1[wid] = sum; s2[wid] = sumsq; }
    __syncthreads();
    if (wid == 0) {
        sum   = lane < 8 ? s1[lane] : 0.f;
        sumsq = lane < 8 ? s2[lane] : 0.f;
        for (int o = 4; o; o >>= 1) {
            sum   += __shfl_down_sync(0xffffffffu, sum, o);
            sumsq += __shfl_down_sync(0xffffffffu, sumsq, o);
        }
        if (lane == 0) { s1[0] = sum; s2[0] = sumsq; }
    }
    __syncthreads();
    float mu  = s1[0] * (1.0f / DDIM);
    float var = s2[0] * (1.0f / DDIM) - mu * mu;
    float inv = rsqrtf(var + 1e-5f);
    size_t base = (size_t)row * DDIM;
    for (int i = threadIdx.x; i < DDIM; i += blockDim.x) {
        float v = (xr[i] - mu) * inv * w[i] + b[i];
        __nv_bfloat16 h = __float2bfloat16_rn(v);
        hi[base + i] = h;
        lo[base + i] = __float2bfloat16_rn(v - __bfloat162float(h));
    }
}

// ---------------- split-bf16 GEMM, CTA tile 256x128, 512 threads ----------------
__global__ void __launch_bounds__(512, 1) gemm3_kernel(
    const __nv_bfloat16* __restrict__ Ah, const __nv_bfloat16* __restrict__ Al,
    long lda, long sAb, long sAhh,
    const __nv_bfloat16* __restrict__ Wh, const __nv_bfloat16* __restrict__ Wl,
    long ldb, long sBb, long sBhh,
    const float* __restrict__ bias, long sbias, const float* __restrict__ resid,
    float* __restrict__ Cf, __nv_bfloat16* __restrict__ Ch, __nv_bfloat16* __restrict__ Cl,
    long ldc, long sCb, long sChh,
    int Kd, float scale, int act, int three)
{
    extern __shared__ __nv_bfloat16 sm[];
    const int SP    = three ? (2 * APLANE + 2 * BPLANE) : (APLANE + BPLANE);
    const int offAl = APLANE;
    const int offBh = three ? 2 * APLANE : APLANE;
    const int offBl = 2 * APLANE + BPLANE;

    const int tid  = threadIdx.x;
    const int lane = tid & 31;
    const int warp = tid >> 5;
    const int wm = warp >> 2, wn = warp & 3;
    const int zb = blockIdx.z / NH, zh = blockIdx.z % NH;
    const size_t Aoff = (size_t)zb * sAb + (size_t)zh * sAhh;
    const size_t Boff = (size_t)zb * sBb + (size_t)zh * sBhh;
    const size_t Coff = (size_t)zb * sCb + (size_t)zh * sChh;
    const size_t bm = (size_t)blockIdx.y * 256, bn = (size_t)blockIdx.x * 128;
    const float* bptr = bias ? bias + (size_t)zh * sbias : nullptr;

    const int lr   = tid >> 2;
    const int lseg = (tid & 3) * 8;
    const __nv_bfloat16* gAh1 = Ah + Aoff + (bm + lr) * (size_t)lda + lseg;
    const __nv_bfloat16* gAh2 = gAh1 + 128 * (size_t)lda;
    const __nv_bfloat16* gAl1 = Al + Aoff + (bm + lr) * (size_t)lda + lseg;
    const __nv_bfloat16* gAl2 = gAl1 + 128 * (size_t)lda;
    const __nv_bfloat16* gBh  = Wh + Boff + (bn + lr) * (size_t)ldb + lseg;
    const __nv_bfloat16* gBl  = Wl + Boff + (bn + lr) * (size_t)ldb + lseg;
    const int soffA1 = lr * GS + lseg;
    const int soffA2 = soffA1 + 128 * GS;
    const int soffB  = lr * GS + lseg;

    const uint32_t smBase = smem_u32(sm);
    const int arow = wm * 64 + (lane & 15);
    const int acol = (lane >> 4) << 3;
    const int bg = lane >> 2;
    const int bt = (lane & 3) << 1;

    float acc[4][4][4];
#pragma unroll
    for (int i = 0; i < 4; i++)
#pragma unroll
        for (int j = 0; j < 4; j++)
#pragma unroll
            for (int t = 0; t < 4; t++) acc[i][j][t] = 0.f;

    const int ntiles = Kd >> 5;

    auto load_stage = [&](int st, int k0) {
        uint32_t base = smBase + (uint32_t)(st * SP) * 2;
        cpa16(base + (uint32_t)soffA1 * 2, gAh1 + k0);
        cpa16(base + (uint32_t)soffA2 * 2, gAh2 + k0);
        cpa16(base + (uint32_t)(offBh + soffB) * 2, gBh + k0);
        if (three) {
            cpa16(base + (uint32_t)(offAl + soffA1) * 2, gAl1 + k0);
            cpa16(base + (uint32_t)(offAl + soffA2) * 2, gAl2 + k0);
            cpa16(base + (uint32_t)(offBl + soffB) * 2, gBl + k0);
        }
    };

    load_stage(0, 0);
    cpa_commit();

    for (int it = 0; it < ntiles; it++) {
        if (it + 1 < ntiles) { load_stage((it + 1) & 1, (it + 1) << 5); cpa_commit(); cpa_wait1(); }
        else cpa_wait0();
        __syncthreads();

        const int st = it & 1;
        const uint32_t aH = smBase + (uint32_t)(st * SP) * 2;
        const uint32_t aL = aH + (uint32_t)offAl * 2;
        const __nv_bfloat16* sBh = sm + st * SP + offBh;
        const __nv_bfloat16* sBl = sm + st * SP + offBl;

#pragma unroll
        for (int ks = 0; ks < 32; ks += 16) {
            uint32_t afh[4][4], afl[4][4];
#pragma unroll
            for (int mi = 0; mi < 4; mi++) {
                uint32_t off = (uint32_t)(((arow + mi * 16) * GS + ks + acol) * 2);
                ldsm_x4(afh[mi], aH + off);
                if (three) ldsm_x4(afl[mi], aL + off);
            }
#pragma unroll
            for (int ni = 0; ni < 4; ni++) {
                int bidx = (wn * 32 + ni * 8 + bg) * GS + ks + bt;
                uint32_t bh0 = *(const uint32_t*)&sBh[bidx];
                uint32_t bh1 = *(const uint32_t*)&sBh[bidx + 8];
#pragma unroll
                for (int mi = 0; mi < 4; mi++)
                    mma_bf16(acc[mi][ni], afh[mi], bh0, bh1);
                if (three) {
                    uint32_t bl0 = *(const uint32_t*)&sBl[bidx];
                    uint32_t bl1 = *(const uint32_t*)&sBl[bidx + 8];
#pragma unroll
                    for (int mi = 0; mi < 4; mi++) {
                        mma_bf16(acc[mi][ni], afl[mi], bh0, bh1);
                        mma_bf16(acc[mi][ni], afh[mi], bl0, bl1);
                    }
                }
            }
        }
        __syncthreads();
    }

    const int gr = lane >> 2;
    const int gc = (lane & 3) << 1;
#pragma unroll
    for (int mi = 0; mi < 4; mi++) {
        size_t r0 = bm + wm * 64 + mi * 16 + gr;
#pragma unroll
        for (int ni = 0; ni < 4; ni++) {
            size_t c0 = bn + wn * 32 + ni * 8 + gc;
            float bv0 = bptr ? bptr[c0] : 0.f;
            float bv1 = bptr ? bptr[c0 + 1] : 0.f;
#pragma unroll
            for (int half = 0; half < 2; half++) {
                size_t row = r0 + half * 8;
                float v0 = acc[mi][ni][half * 2 + 0] * scale + bv0;
                float v1 = acc[mi][ni][half * 2 + 1] * scale + bv1;
                size_t o = Coff + row * ldc + c0;
                if (resid) {
                    float2 rv = *(const float2*)(resid + o);
                    v0 += rv.x; v1 += rv.y;
                }
                if (act) { v0 = gelu_exact(v0); v1 = gelu_exact(v1); }
                if (Cf) *(float2*)(Cf + o) = make_float2(v0, v1);
                if (Ch) {
                    __nv_bfloat16 h0 = __float2bfloat16_rn(v0);
                    __nv_bfloat16 h1 = __float2bfloat16_rn(v1);
                    *(__nv_bfloat162*)(Ch + o) = __nv_bfloat162(h0, h1);
                    *(__nv_bfloat162*)(Cl + o) = __nv_bfloat162(
                        __float2bfloat16_rn(v0 - __bfloat162float(h0)),
                        __float2bfloat16_rn(v1 - __bfloat162float(h1)));
                }
            }
        }
    }
}

// ---------------- fused scores + softmax + head-mean ----------------
// CTA: (b,h, 256 q-rows) x all 1024 keys. Pass 1: online row max + rescaled sum.
// Pass 2: recompute S, emit p (bf16) + atomic head-mean (fp32).
#define SGS 72
#define SAPL (256*SGS)
#define SBPL (128*SGS)
#define TILE_BYTES ((2*SAPL + 4*SBPL) * 2)   /* 147456 */
__global__ void __launch_bounds__(512, 1) attn_softmax_kernel(
    const __nv_bfloat16* __restrict__ qh, const __nv_bfloat16* __restrict__ ql,
    const __nv_bfloat16* __restrict__ kh, const __nv_bfloat16* __restrict__ kl,
    const void* __restrict__ mask,
    __nv_bfloat16* __restrict__ attn, float* __restrict__ mout)
{
    extern __shared__ char smraw[];
    __nv_bfloat16* sm = (__nv_bfloat16*)smraw;
    float* s_m    = (float*)(smraw + TILE_BYTES);     // 256 row maxima
    float* s_inv  = s_m + 256;                        // 256 row 1/sum (pass 2)
    float* s_tmax = s_inv + 256;                      // [4][256]
    float* s_tsum = s_tmax + 1024;                    // [4][256]
    char*  s_msk  = (char*)(s_tsum + 1024);           // 1024

    const int offAl = SAPL;
    const int offB  = 2 * SAPL;
    const int BSTG  = 2 * SBPL;

    const int tid = threadIdx.x, lane = tid & 31, warp = tid >> 5;
    const int wm = warp >> 2, wn = warp & 3;
    const int z = blockIdx.z, b = z / NH, h = z % NH;
    const size_t bm = (size_t)blockIdx.y * 256;
    const __nv_bfloat16* Ah = qh + (size_t)b * QQL * DDIM + h * HDIM;
    const __nv_bfloat16* Al = ql + (size_t)b * QQL * DDIM + h * HDIM;
    const __nv_bfloat16* Bh = kh + (size_t)b * KKL * DDIM + h * HDIM;
    const __nv_bfloat16* Bl = kl + (size_t)b * KKL * DDIM + h * HDIM;
    __nv_bfloat16* Aout = attn + ((size_t)(b * NH + h) * QQL + bm) * KKL;
    float* Mout = mout + ((size_t)b * QQL + bm) * KKL;

    const uint32_t smBase = smem_u32(sm);
    const float NEG = -__int_as_float(0x7f800000);

    // mask -> smem ; init row maxima
    {
        int flag = g_mask_flag;
        for (int i = tid; i < KKL; i += 512)
            s_msk[i] = mask_valid(mask, b * KKL + i, flag) ? 1 : 0;
        if (tid < 256) s_m[tid] = NEG;
    }
    float s_run = 0.f;   // running sum (valid for tid < 256)

    // A tile (persistent, hi+lo)
#pragma unroll
    for (int i = 0; i < 4; i++) {
        int c = tid + 512 * i;
        int row = c >> 3;
        int seg = (c & 7) * 8;
        uint32_t d = smBase + (uint32_t)(row * SGS + seg) * 2;
        cpa16(d, Ah + (bm + row) * (size_t)DDIM + seg);
        cpa16(d + (uint32_t)offAl * 2, Al + (bm + row) * (size_t)DDIM + seg);
    }
    auto load_B = [&](int st, int kt) {
        uint32_t base = smBase + (uint32_t)(offB + st * BSTG) * 2;
#pragma unroll
        for (int i = 0; i < 2; i++) {
            int c = tid + 512 * i;
            int row = c >> 3;
            int seg = (c & 7) * 8;
            uint32_t d = base + (uint32_t)(row * SGS + seg) * 2;
            cpa16(d, Bh + (size_t)(kt * 128 + row) * DDIM + seg);
            cpa16(d + (uint32_t)SBPL * 2, Bl + (size_t)(kt * 128 + row) * DDIM + seg);
        }
    };

    const int arow = wm * 64 + (lane & 15);
    const int acol = (lane >> 4) << 3;
    const int bg = lane >> 2, bt = (lane & 3) << 1;
    const uint32_t aH = smBase;
    const uint32_t aL = smBase + (uint32_t)offAl * 2;
    const int gr = lane >> 2;
    const int gc = (lane & 3) << 1;

    float acc[4][4][4];
    auto mma_tile = [&](int kt) {
#pragma unroll
        for (int i = 0; i < 4; i++)
#pragma unroll
            for (int j = 0; j < 4; j++)
#pragma unroll
                for (int t = 0; t < 4; t++) acc[i][j][t] = 0.f;
        const __nv_bfloat16* sBh = sm + offB + (kt & 1) * BSTG;
        const __nv_bfloat16* sBl = sBh + SBPL;
#pragma unroll
        for (int ks = 0; ks < 64; ks += 16) {
            uint32_t afh[4][4], afl[4][4];
#pragma unroll
            for (int mi = 0; mi < 4; mi++) {
                uint32_t off = (uint32_t)(((arow + mi * 16) * SGS + ks + acol) * 2);
                ldsm_x4(afh[mi], aH + off);
                ldsm_x4(afl[mi], aL + off);
            }
#pragma unroll
            for (int ni = 0; ni < 4; ni++) {
                int bidx = (wn * 32 + ni * 8 + bg) * SGS + ks + bt;
                uint32_t bh0 = *(const uint32_t*)&sBh[bidx];
                uint32_t bh1 = *(const uint32_t*)&sBh[bidx + 8];
                uint32_t bl0 = *(const uint32_t*)&sBl[bidx];
                uint32_t bl1 = *(const uint32_t*)&sBl[bidx + 8];
#pragma unroll
                for (int mi = 0; mi < 4; mi++) {
                    mma_bf16(acc[mi][ni], afh[mi], bh0, bh1);
                    mma_bf16(acc[mi][ni], afl[mi], bh0, bh1);
                    mma_bf16(acc[mi][ni], afh[mi], bl0, bl1);
                }
            }
        }
    };

    // ======== PASS 1: row max + rescaled running sum ========
    load_B(0, 0);
    cpa_commit();
    for (int kt = 0; kt < 8; kt++) {
        if (kt + 1 < 8) { load_B((kt + 1) & 1, kt + 1); cpa_commit(); cpa_wait1(); }
        else cpa_wait0();
        __syncthreads();
        mma_tile(kt);

        // thread-local masked row max (8 rows x 8 cols each)
        float rmax[8];
#pragma unroll
        for (int r8 = 0; r8 < 8; r8++) rmax[r8] = NEG;
#pragma unroll
        for (int mi = 0; mi < 4; mi++)
#pragma unroll
            for (int ni = 0; ni < 4; ni++)
#pragma unroll
                for (int t = 0; t < 4; t++) {
                    int col = kt * 128 + wn * 32 + ni * 8 + gc + (t & 1);
                    float v = s_msk[col] ? acc[mi][ni][t] * 0.125f : NEG;
                    acc[mi][ni][t] = v;
                    int r8 = mi * 2 + (t >> 1);
                    rmax[r8] = fmaxf(rmax[r8], v);
                }
#pragma unroll
        for (int r8 = 0; r8 < 8; r8++) {
            float v = rmax[r8];
            v = fmaxf(v, __shfl_xor_sync(0xffffffffu, v, 1));
            v = fmaxf(v, __shfl_xor_sync(0xffffffffu, v, 2));
            if ((lane & 3) == 0)
                s_tmax[wn * 256 + wm * 64 + (r8 >> 1) * 16 + (r8 & 1) * 8 + gr] = v;
        }
        __syncthreads();

        if (tid < 256) {
            float tm = fmaxf(fmaxf(s_tmax[tid], s_tmax[256 + tid]),
                             fmaxf(s_tmax[512 + tid], s_tmax[768 + tid]));
            float old = s_m[tid];
            float nm = fmaxf(old, tm);
            float sc = (old > NEG) ? __expf(old - nm) : 0.f;
            s_run *= sc;
            s_m[tid] = nm;
        }
        __syncthreads();

        // exp + row partial sums
        float rsum[8];
#pragma unroll
        for (int r8 = 0; r8 < 8; r8++) rsum[r8] = 0.f;
#pragma unroll
        for (int mi = 0; mi < 4; mi++) {
#pragma unroll
            for (int t4 = 0; t4 < 2; t4++) {
                int row = wm * 64 + mi * 16 + t4 * 8 + gr;
                float mrow = s_m[row];
                float e0 = 0.f;
#pragma unroll
                for (int ni = 0; ni < 4; ni++) {
                    e0 += __expf(acc[mi][ni][t4 * 2 + 0] - mrow);
                    e0 += __expf(acc[mi][ni][t4 * 2 + 1] - mrow);
                }
                rsum[mi * 2 + t4] = e0;
            }
        }
#pragma unroll
        for (int r8 = 0; r8 < 8; r8++) {
            float v = rsum[r8];
            v += __shfl_xor_sync(0xffffffffu, v, 1);
            v += __shfl_xor_sync(0xffffffffu, v, 2);
            if ((lane & 3) == 0)
                s_tsum[wn * 256 + wm * 64 + (r8 >> 1) * 16 + (r8 & 1) * 8 + gr] = v;
        }
        __syncthreads();
        if (tid < 256)
            s_run += s_tsum[tid] + s_tsum[256 + tid] + s_tsum[512 + tid] + s_tsum[768 + tid];
    }
    if (tid < 256) s_inv[tid] = 1.0f / s_run;
    __syncthreads();

    // ======== PASS 2: recompute, emit p + head-mean atomics ========
    load_B(0, 0);
    cpa_commit();
    for (int kt = 0; kt < 8; kt++) {
        if (kt + 1 < 8) { load_B((kt + 1) & 1, kt + 1); cpa_commit(); cpa_wait1(); }
        else cpa_wait0();
        __syncthreads();
        mma_tile(kt);

#pragma unroll
        for (int mi = 0; mi < 4; mi++) {
#pragma unroll
            for (int t4 = 0; t4 < 2; t4++) {
                int row = wm * 64 + mi * 16 + t4 * 8 + gr;
                float mrow = s_m[row];
                float inv = s_inv[row];
#pragma unroll
                for (int ni = 0; ni < 4; ni++) {
                    int col = kt * 128 + wn * 32 + ni * 8 + gc;
                    float v0 = s_msk[col]     ? acc[mi][ni][t4 * 2 + 0] * 0.125f : NEG;
                    float v1 = s_msk[col + 1] ? acc[mi][ni][t4 * 2 + 1] * 0.125f : NEG;
                    float p0 = __expf(v0 - mrow) * inv;
                    float p1 = __expf(v1 - mrow) * inv;
                    *(__nv_bfloat162*)(Aout + (size_t)row * KKL + col) =
                        __nv_bfloat162(__float2bfloat16_rn(p0), __float2bfloat16_rn(p1));
                    atomicAdd(Mout + (size_t)row * KKL + col,     p0 * (1.0f / NH));
                    atomicAdd(Mout + (size_t)row * KKL + col + 1, p1 * (1.0f / NH));
                }
            }
        }
        __syncthreads();
    }
}

// ---------------- transpose V (fp32 -> bf16, [b,k,c] -> [b,c,k]) ----------------
__global__ void __launch_bounds__(256) transpose_split_kernel(
    const float* __restrict__ v, __nv_bfloat16* __restrict__ th)
{
    __shared__ float tile[32][33];
    int tx = threadIdx.x, ty = threadIdx.y;
    int c0 = blockIdx.x * 32;
    int r0 = blockIdx.y * 32;
#pragma unroll
    for (int i = 0; i < 4; i++)
        tile[ty + i * 8][tx] = v[(size_t)(r0 + ty + i * 8) * DDIM + c0 + tx];
    __syncthreads();
    int b = r0 >> 10;
    int kk0 = r0 & 1023;
#pragma unroll
    for (int i = 0; i < 4; i++) {
        float val = tile[tx][ty + i * 8];
        size_t o = ((size_t)(b << 10) + c0 + ty + i * 8) * 1024 + kk0 + tx;
        th[o] = __float2bfloat16_rn(val);
    }
}

// ---------------- AV (mma.sync, 1-pass bf16, cp.async 2-stage) ----------------
#define AVP (128*GS)
#define BVP (64*GS)
__global__ void __launch_bounds__(256, 2) av_kernel(
    const __nv_bfloat16* __restrict__ attn, const __nv_bfloat16* __restrict__ vt,
    __nv_bfloat16* __restrict__ Ch)
{
    __shared__ __nv_bfloat16 sm[2 * (AVP + BVP)];
    const int tid = threadIdx.x;
    const int lane = tid & 31;
    const int warp = tid >> 5;
    const int wm = warp >> 2, wn = warp & 3;
    const int z = blockIdx.z;
    const int b = z / NH, h = z % NH;
    const size_t bm = (size_t)blockIdx.y * 128;

    const __nv_bfloat16* A = attn + (size_t)z * QQL * KKL;
    const __nv_bfloat16* W = vt + ((size_t)b * 1024 + h * 64) * 1024;
    const size_t Coff = (size_t)b * QQL * DDIM + h * HDIM;

    const int lrow = tid >> 1;
    const int lseg = (tid & 1) * 16;
    const __nv_bfloat16* gA = A + (bm + lrow) * (size_t)KKL + lseg;
    const int soffA = lrow * GS + lseg;
    const int brow = tid >> 2;
    const int bseg = (tid & 3) * 8;
    const __nv_bfloat16* gB = W + (size_t)brow * 1024 + bseg;
    const int soffB = brow * GS + bseg;

    const uint32_t smBase = smem_u32(sm);
    const int arow = wm * 64 + (lane & 15);
    const int acol = (lane >> 4) << 3;
    const int bg = lane >> 2;
    const int bt = (lane & 3) << 1;
    const int SP2 = AVP + BVP;

    float acc[4][2][4];
#pragma unroll
    for (int i = 0; i < 4; i++)
#pragma unroll
        for (int jq = 0; jq < 2; jq++)
#pragma unroll
            for (int t = 0; t < 4; t++) acc[i][jq][t] = 0.f;

    auto load_stage = [&](int st, int k0) {
        uint32_t d = smBase + (uint32_t)(st * SP2 + soffA) * 2;
        cpa16(d,      gA + k0);
        cpa16(d + 16, gA + k0 + 8);
        uint32_t db = smBase + (uint32_t)(st * SP2 + AVP + soffB) * 2;
        cpa16(db, gB + k0);
    };

    load_stage(0, 0);
    cpa_commit();

    for (int it = 0; it < 32; it++) {
        if (it + 1 < 32) { load_stage((it + 1) & 1, (it + 1) << 5); cpa_commit(); cpa_wait1(); }
        else cpa_wait0();
        __syncthreads();

        const int st = it & 1;
        const uint32_t aBase = smBase + (uint32_t)(st * SP2) * 2;
        const __nv_bfloat16* sB = sm + st * SP2 + AVP;

#pragma unroll
        for (int ks = 0; ks < 32; ks += 16) {
            uint32_t af[4][4];
#pragma unroll
            for (int mi = 0; mi < 4; mi++) {
                uint32_t off = (uint32_t)(((arow + mi * 16) * GS + ks + acol) * 2);
                ldsm_x4(af[mi], aBase + off);
            }
#pragma unroll
            for (int ni = 0; ni < 2; ni++) {
                int bidx = (wn * 16 + ni * 8 + bg) * GS + ks + bt;
                uint32_t b0 = *(const uint32_t*)&sB[bidx];
                uint32_t b1 = *(const uint32_t*)&sB[bidx + 8];
#pragma unroll
                for (int mi = 0; mi < 4; mi++)
                    mma_bf16(acc[mi][ni], af[mi], b0, b1);
            }
        }
        __syncthreads();
    }

    const int gr = lane >> 2;
    const int gc = (lane & 3) << 1;
#pragma unroll
    for (int mi = 0; mi < 4; mi++) {
        size_t r0 = bm + wm * 64 + mi * 16 + gr;
#pragma unroll
        for (int ni = 0; ni < 2; ni++) {
            int c0 = wn * 16 + ni * 8 + gc;
#pragma unroll
            for (int half = 0; half < 2; half++) {
                size_t row = r0 + half * 8;
                size_t o = Coff + row * DDIM + c0;
                *(__nv_bfloat162*)(Ch + o) = __nv_bfloat162(
                    __float2bfloat16_rn(acc[mi][ni][half * 2 + 0]),
                    __float2bfloat16_rn(acc[mi][ni][half * 2 + 1]));
            }
        }
    }
}

// ---------------- launch ----------------
extern "C" void kernel_launch(void* const* d_in, const int* in_sizes, int n_in,
                              void* d_out, int out_size)
{
    const float* query      = (const float*)d_in[0];
    const float* key_value  = (const float*)d_in[1];
    const void*  kpm        = d_in[2];
    const float* ln_q_w     = (const float*)d_in[3];
    const float* ln_q_b     = (const float*)d_in[4];
    const float* ln_kv_w    = (const float*)d_in[5];
    const float* ln_kv_b    = (const float*)d_in[6];
    const float* ln_f_w     = (const float*)d_in[7];
    const float* ln_f_b     = (const float*)d_in[8];
    const float* in_proj_w  = (const float*)d_in[9];
    const float* in_proj_b  = (const float*)d_in[10];
    const float* out_proj_w = (const float*)d_in[11];
    const float* out_proj_b = (const float*)d_in[12];
    const float* ffn_w1     = (const float*)d_in[13];
    const float* ffn_b1     = (const float*)d_in[14];
    const float* ffn_w2     = (const float*)d_in[15];
    const float* ffn_b2     = (const float*)d_in[16];

    float* out_x    = (float*)d_out;
    float* out_attn = out_x + (size_t)BB * QQL * DDIM;

    __nv_bfloat16 *xnh, *xnl, *qkph, *qkpl, *lnfh, *lnfl, *aoh, *hh, *hl, *wh, *wl;
    __nv_bfloat16 *vth, *ath;
    float *vp, *xb;
    cudaGetSymbolAddress((void**)&xnh,  g_xn_h);  cudaGetSymbolAddress((void**)&xnl,  g_xn_l);
    cudaGetSymbolAddress((void**)&qkph, g_qkp_h); cudaGetSymbolAddress((void**)&qkpl, g_qkp_l);
    cudaGetSymbolAddress((void**)&lnfh, g_lnf_h); cudaGetSymbolAddress((void**)&lnfl, g_lnf_l);
    cudaGetSymbolAddress((void**)&aoh,  g_ao_h);
    cudaGetSymbolAddress((void**)&hh,   g_hh);    cudaGetSymbolAddress((void**)&hl,   g_hl);
    cudaGetSymbolAddress((void**)&wh,   g_w_h);   cudaGetSymbolAddress((void**)&wl,   g_w_l);
    cudaGetSymbolAddress((void**)&vth,  g_vt_h);
    cudaGetSymbolAddress((void**)&ath,  g_attn_h);
    cudaGetSymbolAddress((void**)&vp,   g_v);
    cudaGetSymbolAddress((void**)&xb,   g_x);

    const size_t M1 = (size_t)1024 * 1024;
    const size_t MD = (size_t)MROWS * DDIM;
    const size_t OFF_OUT  = 3 * M1;
    const size_t OFF_FFN1 = 4 * M1;
    const size_t OFF_FFN2 = 8 * M1;

    const int SM3 = 2 * (2 * APLANE + 2 * BPLANE) * 2;   // 122880 B
    const int SM1 = 2 * (APLANE + BPLANE) * 2;           //  61440 B
    const int SMS = TILE_BYTES + 256 * 4 * 2 + 1024 * 4 * 2 + 1024 + 256;  // tiles + stats + mask
    cudaFuncSetAttribute(gemm3_kernel,         cudaFuncAttributeMaxDynamicSharedMemorySize, SM3);
    cudaFuncSetAttribute(attn_softmax_kernel,  cudaFuncAttributeMaxDynamicSharedMemorySize, SMS);

    detect_mask_kernel<<<1, 256>>>((const unsigned char*)kpm);

    // zero the head-mean output (accumulated via atomics)
    cudaMemsetAsync(out_attn, 0, (size_t)BB * QQL * KKL * sizeof(float));

    split_kernel<<<(unsigned)(3 * M1 / 1024), 256>>>(in_proj_w,  wh,            wl,            3 * M1);
    split_kernel<<<(unsigned)(1 * M1 / 1024), 256>>>(out_proj_w, wh + OFF_OUT,  wl + OFF_OUT,  1 * M1);
    split_kernel<<<(unsigned)(4 * M1 / 1024), 256>>>(ffn_w1,     wh + OFF_FFN1, wl + OFF_FFN1, 4 * M1);
    split_kernel<<<(unsigned)(4 * M1 / 1024), 256>>>(ffn_w2,     wh + OFF_FFN2, wl + OFF_FFN2, 4 * M1);

    ln_split_kernel<<<MROWS, 256>>>(query,     ln_q_w,  ln_q_b,  xnh,      xnl);
    ln_split_kernel<<<MROWS, 256>>>(key_value, ln_kv_w, ln_kv_b, xnh + MD, xnl + MD);

    // merged q+k proj (3-pass, z=2)
    dim3 gqk(DDIM / 128, MROWS / 256, 2);
    gemm3_kernel<<<gqk, 512, SM3>>>(xnh, xnl, DDIM, 0, (long)MD,
                                    wh, wl, DDIM, 0, (long)M1,
                                    in_proj_b, DDIM, nullptr,
                                    nullptr, qkph, qkpl, DDIM, 0, (long)MD,
                                    DDIM, 1.f, 0, 1);
    // v proj (1-pass -> fp32)
    dim3 g1024(DDIM / 128, MROWS / 256, 1);
    gemm3_kernel<<<g1024, 512, SM1>>>(xnh + MD, xnh + MD, DDIM, 0, 0,
                                      wh + 2 * M1, wh + 2 * M1, DDIM, 0, 0,
                                      in_proj_b + 2 * DDIM, 0, nullptr,
                                      vp, nullptr, nullptr, DDIM, 0, 0,
                                      DDIM, 1.f, 0, 0);
    transpose_split_kernel<<<dim3(DDIM / 32, MROWS / 32), dim3(32, 8)>>>(vp, vth);

    // fused scores + softmax + head-mean
    dim3 gsc(1, QQL / 256, BB * NH);
    attn_softmax_kernel<<<gsc, 512, SMS>>>(qkph, qkpl, qkph + MD, qkpl + MD, kpm, ath, out_attn);

    dim3 gav(1, QQL / 128, BB * NH);
    av_kernel<<<gav, 256>>>(ath, vth, aoh);

    // out_proj + residual (1-pass -> fp32)
    gemm3_kernel<<<g1024, 512, SM1>>>(aoh, aoh, DDIM, 0, 0,
                                      wh + OFF_OUT, wh + OFF_OUT, DDIM, 0, 0,
                                      out_proj_b, 0, query,
                                      xb, nullptr, nullptr, DDIM, 0, 0,
                                      DDIM, 1.f, 0, 0);

    ln_split_kernel<<<MROWS, 256>>>(xb, ln_f_w, ln_f_b, lnfh, lnfl);

    // ffn1 (3-pass, gelu -> bf16 hi/lo)
    dim3 gff1(FFD / 128, MROWS / 256, 1);
    gemm3_kernel<<<gff1, 512, SM3>>>(lnfh, lnfl, DDIM, 0, 0,
                                     wh + OFF_FFN1, wl + OFF_FFN1, DDIM, 0, 0,
                                     ffn_b1, 0, nullptr,
                                     nullptr, hh, hl, FFD, 0, 0,
                                     DDIM, 1.f, 1, 1);
    // ffn2 (3-pass, residual -> fp32)
    gemm3_kernel<<<g1024, 512, SM3>>>(hh, hl, FFD, 0, 0,
                                      wh + OFF_FFN2, wl + OFF_FFN2, FFD, 0, 0,
                                      ffn_b2, 0, xb,
                                      out_x, nullptr, nullptr, DDIM, 0, 0,
                                      FFD, 1.f, 0, 1);
}

// round 12
// speedup vs baseline: 1.6109x; 1.6109x over previous
#include <cuda_runtime.h>
#include <cuda_bf16.h>
#include <cuda_fp16.h>
#include <math.h>
#include <stdint.h>

#define BB 8
#define QQL 1024
#define KKL 1024
#define DDIM 1024
#define NH 16
#define HDIM 64
#define FFD 4096
#define MROWS (BB*QQL)   /* 8192 */
#define GS 40            /* smem row stride (2B elems) */
#define APLANE (256*GS)
#define BPLANE (128*GS)

// ---------------- scratch (device globals) ----------------
__device__ __nv_bfloat16 g_xn_h[(size_t)2 * MROWS * DDIM],  g_xn_l[(size_t)2 * MROWS * DDIM];
__device__ __nv_bfloat16 g_qkp_h[(size_t)2 * MROWS * DDIM], g_qkp_l[(size_t)2 * MROWS * DDIM];
__device__ __half        g_lnf16[(size_t)MROWS * DDIM];
__device__ __nv_bfloat16 g_vt_h[(size_t)MROWS * DDIM];
__device__ __nv_bfloat16 g_ao_h[(size_t)MROWS * DDIM];
__device__ __half        g_h16[(size_t)MROWS * FFD];
__device__ __nv_bfloat16 g_w_h[(size_t)4 * 1024 * 1024], g_w_l[(size_t)4 * 1024 * 1024];
__device__ __half        g_w16[(size_t)8 * 1024 * 1024];
__device__ __nv_bfloat16 g_attn_h[(size_t)BB * NH * QQL * KKL];   // 256 MB
__device__ float g_v[(size_t)MROWS * DDIM];
__device__ float g_scores[(size_t)BB * NH * QQL * KKL];           // 512 MB
__device__ float g_x[(size_t)MROWS * DDIM];
__device__ int   g_mask_flag;

// ---------------- helpers ----------------
__device__ __forceinline__ uint32_t smem_u32(const void* p) {
    return (uint32_t)__cvta_generic_to_shared(p);
}
__device__ __forceinline__ void cpa16(uint32_t dst, const void* src) {
    asm volatile("cp.async.cg.shared.global [%0], [%1], 16;\n" :: "r"(dst), "l"(src));
}
__device__ __forceinline__ void cpa_commit() { asm volatile("cp.async.commit_group;\n"); }
__device__ __forceinline__ void cpa_wait0() { asm volatile("cp.async.wait_group 0;\n"); }
__device__ __forceinline__ void cpa_wait1() { asm volatile("cp.async.wait_group 1;\n"); }

__device__ __forceinline__ void mma_bf16(float* c, const uint32_t* a, uint32_t b0, uint32_t b1) {
    asm volatile(
        "mma.sync.aligned.m16n8k16.row.col.f32.bf16.bf16.f32 "
        "{%0,%1,%2,%3}, {%4,%5,%6,%7}, {%8,%9}, {%0,%1,%2,%3};\n"
        : "+f"(c[0]), "+f"(c[1]), "+f"(c[2]), "+f"(c[3])
        : "r"(a[0]), "r"(a[1]), "r"(a[2]), "r"(a[3]), "r"(b0), "r"(b1));
}
__device__ __forceinline__ void mma_fp16(float* c, const uint32_t* a, uint32_t b0, uint32_t b1) {
    asm volatile(
        "mma.sync.aligned.m16n8k16.row.col.f32.f16.f16.f32 "
        "{%0,%1,%2,%3}, {%4,%5,%6,%7}, {%8,%9}, {%0,%1,%2,%3};\n"
        : "+f"(c[0]), "+f"(c[1]), "+f"(c[2]), "+f"(c[3])
        : "r"(a[0]), "r"(a[1]), "r"(a[2]), "r"(a[3]), "r"(b0), "r"(b1));
}
__device__ __forceinline__ void ldsm_x4(uint32_t* r, uint32_t addr) {
    asm volatile("ldmatrix.sync.aligned.m8n8.x4.shared.b16 {%0,%1,%2,%3}, [%4];\n"
                 : "=r"(r[0]), "=r"(r[1]), "=r"(r[2]), "=r"(r[3]) : "r"(addr));
}
__device__ __forceinline__ float gelu_exact(float v) {
    return 0.5f * v * (1.0f + erff(v * 0.70710678118654752f));
}

// ---------------- mask dtype sniffing ----------------
__global__ void detect_mask_kernel(const unsigned char* __restrict__ m) {
    __shared__ int c1, c2, c3;
    if (threadIdx.x == 0) { c1 = 0; c2 = 0; c3 = 0; }
    __syncthreads();
    for (int i = threadIdx.x; i < BB * KKL; i += blockDim.x) {
        unsigned char v = m[i];
        if (v) {
            int p = i & 3;
            if (p == 1) atomicAdd(&c1, 1);
            else if (p == 2) atomicAdd(&c2, 1);
            else if (p == 3) atomicAdd(&c3, 1);
        }
    }
    __syncthreads();
    if (threadIdx.x == 0) {
        int f;
        if (c1 == 0 && c2 == 0 && c3 == 0) f = 0;  // int32
        else if (c1 == 0) f = 2;                   // float32
        else f = 1;                                // uint8
        g_mask_flag = f;
    }
}

__device__ __forceinline__ bool mask_valid(const void* m, int idx, int flag) {
    if (flag == 1) return ((const unsigned char*)m)[idx] != 0;
    if (flag == 2) return ((const float*)m)[idx] != 0.0f;
    return ((const int*)m)[idx] != 0;
}

// ---------------- split fp32 -> bf16 hi/lo ----------------
__global__ void __launch_bounds__(256) split_kernel(
    const float* __restrict__ x, __nv_bfloat16* __restrict__ hi,
    __nv_bfloat16* __restrict__ lo, size_t n)
{
    size_t i = ((size_t)blockIdx.x * 256 + threadIdx.x) * 4;
    if (i >= n) return;
    float4 v = *(const float4*)(x + i);
    __nv_bfloat16 h0 = __float2bfloat16_rn(v.x);
    __nv_bfloat16 h1 = __float2bfloat16_rn(v.y);
    __nv_bfloat16 h2 = __float2bfloat16_rn(v.z);
    __nv_bfloat16 h3 = __float2bfloat16_rn(v.w);
    __nv_bfloat162* hp = (__nv_bfloat162*)(hi + i);
    hp[0] = __nv_bfloat162(h0, h1);
    hp[1] = __nv_bfloat162(h2, h3);
    __nv_bfloat162* lp = (__nv_bfloat162*)(lo + i);
    lp[0] = __nv_bfloat162(__float2bfloat16_rn(v.x - __bfloat162float(h0)),
                           __float2bfloat16_rn(v.y - __bfloat162float(h1)));
    lp[1] = __nv_bfloat162(__float2bfloat16_rn(v.z - __bfloat162float(h2)),
                           __float2bfloat16_rn(v.w - __bfloat162float(h3)));
}

// ---------------- convert fp32 -> fp16 ----------------
__global__ void __launch_bounds__(256) tofp16_kernel(
    const float* __restrict__ x, __half* __restrict__ out, size_t n)
{
    size_t i = ((size_t)blockIdx.x * 256 + threadIdx.x) * 4;
    if (i >= n) return;
    float4 v = *(const float4*)(x + i);
    __half2* op = (__half2*)(out + i);
    op[0] = __floats2half2_rn(v.x, v.y);
    op[1] = __floats2half2_rn(v.z, v.w);
}

// ---------------- layernorm -> split bf16 hi/lo ----------------
__global__ void __launch_bounds__(256) ln_split_kernel(
    const float* __restrict__ x, const float* __restrict__ w,
    const float* __restrict__ b, __nv_bfloat16* __restrict__ hi,
    __nv_bfloat16* __restrict__ lo)
{
    int row = blockIdx.x;
    const float* xr = x + (size_t)row * DDIM;
    float sum = 0.f, sumsq = 0.f;
    for (int i = threadIdx.x; i < DDIM; i += blockDim.x) {
        float v = xr[i]; sum += v; sumsq += v * v;
    }
    __shared__ float s1[32], s2[32];
    for (int o = 16; o; o >>= 1) {
        sum   += __shfl_down_sync(0xffffffffu, sum, o);
        sumsq += __shfl_down_sync(0xffffffffu, sumsq, o);
    }
    int lane = threadIdx.x & 31, wid = threadIdx.x >> 5;
    if (lane == 0) { s1[wid] = sum; s2[wid] = sumsq; }
    __syncthreads();
    if (wid == 0) {
        sum   = lane < 8 ? s1[lane] : 0.f;
        sumsq = lane < 8 ? s2[lane] : 0.f;
        for (int o = 4; o; o >>= 1) {
            sum   += __shfl_down_sync(0xffffffffu, sum, o);
            sumsq += __shfl_down_sync(0xffffffffu, sumsq, o);
        }
        if (lane == 0) { s1[0] = sum; s2[0] = sumsq; }
    }
    __syncthreads();
    float mu  = s1[0] * (1.0f / DDIM);
    float var = s2[0] * (1.0f / DDIM) - mu * mu;
    float inv = rsqrtf(var + 1e-5f);
    size_t base = (size_t)row * DDIM;
    for (int i = threadIdx.x; i < DDIM; i += blockDim.x) {
        float v = (xr[i] - mu) * inv * w[i] + b[i];
        __nv_bfloat16 h = __float2bfloat16_rn(v);
        hi[base + i] = h;
        lo[base + i] = __float2bfloat16_rn(v - __bfloat162float(h));
    }
}

// ---------------- layernorm -> fp16 ----------------
__global__ void __launch_bounds__(256) ln_fp16_kernel(
    const float* __restrict__ x, const float* __restrict__ w,
    const float* __restrict__ b, __half* __restrict__ out)
{
    int row = blockIdx.x;
    const float* xr = x + (size_t)row * DDIM;
    float sum = 0.f, sumsq = 0.f;
    for (int i = threadIdx.x; i < DDIM; i += blockDim.x) {
        float v = xr[i]; sum += v; sumsq += v * v;
    }
    __shared__ float s1[32], s2[32];
    for (int o = 16; o; o >>= 1) {
        sum   += __shfl_down_sync(0xffffffffu, sum, o);
        sumsq += __shfl_down_sync(0xffffffffu, sumsq, o);
    }
    int lane = threadIdx.x & 31, wid = threadIdx.x >> 5;
    if (lane == 0) { s1[wid] = sum; s2[wid] = sumsq; }
    __syncthreads();
    if (wid == 0) {
        sum   = lane < 8 ? s1[lane] : 0.f;
        sumsq = lane < 8 ? s2[lane] : 0.f;
        for (int o = 4; o; o >>= 1) {
            sum   += __shfl_down_sync(0xffffffffu, sum, o);
            sumsq += __shfl_down_sync(0xffffffffu, sumsq, o);
        }
        if (lane == 0) { s1[0] = sum; s2[0] = sumsq; }
    }
    __syncthreads();
    float mu  = s1[0] * (1.0f / DDIM);
    float var = s2[0] * (1.0f / DDIM) - mu * mu;
    float inv = rsqrtf(var + 1e-5f);
    size_t base = (size_t)row * DDIM;
    for (int i = threadIdx.x; i < DDIM; i += blockDim.x) {
        float v = (xr[i] - mu) * inv * w[i] + b[i];
        out[base + i] = __float2half_rn(v);
    }
}

// ---------------- split-bf16 GEMM, CTA tile 256x128, 512 threads ----------------
__global__ void __launch_bounds__(512, 1) gemm3_kernel(
    const __nv_bfloat16* __restrict__ Ah, const __nv_bfloat16* __restrict__ Al,
    long lda, long sAb, long sAhh,
    const __nv_bfloat16* __restrict__ Wh, const __nv_bfloat16* __restrict__ Wl,
    long ldb, long sBb, long sBhh,
    const float* __restrict__ bias, long sbias, const float* __restrict__ resid,
    float* __restrict__ Cf, __nv_bfloat16* __restrict__ Ch, __nv_bfloat16* __restrict__ Cl,
    long ldc, long sCb, long sChh,
    int Kd, float scale, int act, int three)
{
    extern __shared__ __nv_bfloat16 sm[];
    const int SP    = three ? (2 * APLANE + 2 * BPLANE) : (APLANE + BPLANE);
    const int offAl = APLANE;
    const int offBh = three ? 2 * APLANE : APLANE;
    const int offBl = 2 * APLANE + BPLANE;

    const int tid  = threadIdx.x;
    const int lane = tid & 31;
    const int warp = tid >> 5;
    const int wm = warp >> 2, wn = warp & 3;
    const int zb = blockIdx.z / NH, zh = blockIdx.z % NH;
    const size_t Aoff = (size_t)zb * sAb + (size_t)zh * sAhh;
    const size_t Boff = (size_t)zb * sBb + (size_t)zh * sBhh;
    const size_t Coff = (size_t)zb * sCb + (size_t)zh * sChh;
    const size_t bm = (size_t)blockIdx.y * 256, bn = (size_t)blockIdx.x * 128;
    const float* bptr = bias ? bias + (size_t)zh * sbias : nullptr;

    const int lr   = tid >> 2;
    const int lseg = (tid & 3) * 8;
    const __nv_bfloat16* gAh1 = Ah + Aoff + (bm + lr) * (size_t)lda + lseg;
    const __nv_bfloat16* gAh2 = gAh1 + 128 * (size_t)lda;
    const __nv_bfloat16* gAl1 = Al + Aoff + (bm + lr) * (size_t)lda + lseg;
    const __nv_bfloat16* gAl2 = gAl1 + 128 * (size_t)lda;
    const __nv_bfloat16* gBh  = Wh + Boff + (bn + lr) * (size_t)ldb + lseg;
    const __nv_bfloat16* gBl  = Wl + Boff + (bn + lr) * (size_t)ldb + lseg;
    const int soffA1 = lr * GS + lseg;
    const int soffA2 = soffA1 + 128 * GS;
    const int soffB  = lr * GS + lseg;

    const uint32_t smBase = smem_u32(sm);
    const int arow = wm * 64 + (lane & 15);
    const int acol = (lane >> 4) << 3;
    const int bg = lane >> 2;
    const int bt = (lane & 3) << 1;

    float acc[4][4][4];
#pragma unroll
    for (int i = 0; i < 4; i++)
#pragma unroll
        for (int j = 0; j < 4; j++)
#pragma unroll
            for (int t = 0; t < 4; t++) acc[i][j][t] = 0.f;

    const int ntiles = Kd >> 5;

    auto load_stage = [&](int st, int k0) {
        uint32_t base = smBase + (uint32_t)(st * SP) * 2;
        cpa16(base + (uint32_t)soffA1 * 2, gAh1 + k0);
        cpa16(base + (uint32_t)soffA2 * 2, gAh2 + k0);
        cpa16(base + (uint32_t)(offBh + soffB) * 2, gBh + k0);
        if (three) {
            cpa16(base + (uint32_t)(offAl + soffA1) * 2, gAl1 + k0);
            cpa16(base + (uint32_t)(offAl + soffA2) * 2, gAl2 + k0);
            cpa16(base + (uint32_t)(offBl + soffB) * 2, gBl + k0);
        }
    };

    load_stage(0, 0);
    cpa_commit();

    for (int it = 0; it < ntiles; it++) {
        if (it + 1 < ntiles) { load_stage((it + 1) & 1, (it + 1) << 5); cpa_commit(); cpa_wait1(); }
        else cpa_wait0();
        __syncthreads();

        const int st = it & 1;
        const uint32_t aH = smBase + (uint32_t)(st * SP) * 2;
        const uint32_t aL = aH + (uint32_t)offAl * 2;
        const __nv_bfloat16* sBh = sm + st * SP + offBh;
        const __nv_bfloat16* sBl = sm + st * SP + offBl;

#pragma unroll
        for (int ks = 0; ks < 32; ks += 16) {
            uint32_t afh[4][4], afl[4][4];
#pragma unroll
            for (int mi = 0; mi < 4; mi++) {
                uint32_t off = (uint32_t)(((arow + mi * 16) * GS + ks + acol) * 2);
                ldsm_x4(afh[mi], aH + off);
                if (three) ldsm_x4(afl[mi], aL + off);
            }
#pragma unroll
            for (int ni = 0; ni < 4; ni++) {
                int bidx = (wn * 32 + ni * 8 + bg) * GS + ks + bt;
                uint32_t bh0 = *(const uint32_t*)&sBh[bidx];
                uint32_t bh1 = *(const uint32_t*)&sBh[bidx + 8];
#pragma unroll
                for (int mi = 0; mi < 4; mi++)
                    mma_bf16(acc[mi][ni], afh[mi], bh0, bh1);
                if (three) {
                    uint32_t bl0 = *(const uint32_t*)&sBl[bidx];
                    uint32_t bl1 = *(const uint32_t*)&sBl[bidx + 8];
#pragma unroll
                    for (int mi = 0; mi < 4; mi++) {
                        mma_bf16(acc[mi][ni], afl[mi], bh0, bh1);
                        mma_bf16(acc[mi][ni], afh[mi], bl0, bl1);
                    }
                }
            }
        }
        __syncthreads();
    }

    const int gr = lane >> 2;
    const int gc = (lane & 3) << 1;
#pragma unroll
    for (int mi = 0; mi < 4; mi++) {
        size_t r0 = bm + wm * 64 + mi * 16 + gr;
#pragma unroll
        for (int ni = 0; ni < 4; ni++) {
            size_t c0 = bn + wn * 32 + ni * 8 + gc;
            float bv0 = bptr ? bptr[c0] : 0.f;
            float bv1 = bptr ? bptr[c0 + 1] : 0.f;
#pragma unroll
            for (int half = 0; half < 2; half++) {
                size_t row = r0 + half * 8;
                float v0 = acc[mi][ni][half * 2 + 0] * scale + bv0;
                float v1 = acc[mi][ni][half * 2 + 1] * scale + bv1;
                size_t o = Coff + row * ldc + c0;
                if (resid) {
                    float2 rv = *(const float2*)(resid + o);
                    v0 += rv.x; v1 += rv.y;
                }
                if (act) { v0 = gelu_exact(v0); v1 = gelu_exact(v1); }
                if (Cf) *(float2*)(Cf + o) = make_float2(v0, v1);
                if (Ch) {
                    __nv_bfloat16 h0 = __float2bfloat16_rn(v0);
                    __nv_bfloat16 h1 = __float2bfloat16_rn(v1);
                    *(__nv_bfloat162*)(Ch + o) = __nv_bfloat162(h0, h1);
                    *(__nv_bfloat162*)(Cl + o) = __nv_bfloat162(
                        __float2bfloat16_rn(v0 - __bfloat162float(h0)),
                        __float2bfloat16_rn(v1 - __bfloat162float(h1)));
                }
            }
        }
    }
}

// ---------------- fp16 1-pass GEMM (FFN), CTA tile 256x128, 512 threads ----------------
__global__ void __launch_bounds__(512, 1) gemm_fp16_kernel(
    const __half* __restrict__ A, long lda,
    const __half* __restrict__ W, long ldb,
    const float* __restrict__ bias, const float* __restrict__ resid,
    float* __restrict__ Cf, __half* __restrict__ Chf,
    long ldc, int Kd, int act)
{
    extern __shared__ __half smh[];
    const int SP = APLANE + BPLANE;
    const int offB = APLANE;

    const int tid  = threadIdx.x;
    const int lane = tid & 31;
    const int warp = tid >> 5;
    const int wm = warp >> 2, wn = warp & 3;
    const size_t bm = (size_t)blockIdx.y * 256, bn = (size_t)blockIdx.x * 128;

    const int lr   = tid >> 2;
    const int lseg = (tid & 3) * 8;
    const __half* gA1 = A + (bm + lr) * (size_t)lda + lseg;
    const __half* gA2 = gA1 + 128 * (size_t)lda;
    const __half* gB  = W + (bn + lr) * (size_t)ldb + lseg;
    const int soffA1 = lr * GS + lseg;
    const int soffA2 = soffA1 + 128 * GS;
    const int soffB  = lr * GS + lseg;

    const uint32_t smBase = smem_u32(smh);
    const int arow = wm * 64 + (lane & 15);
    const int acol = (lane >> 4) << 3;
    const int bg = lane >> 2;
    const int bt = (lane & 3) << 1;

    float acc[4][4][4];
#pragma unroll
    for (int i = 0; i < 4; i++)
#pragma unroll
        for (int j = 0; j < 4; j++)
#pragma unroll
            for (int t = 0; t < 4; t++) acc[i][j][t] = 0.f;

    const int ntiles = Kd >> 5;

    auto load_stage = [&](int st, int k0) {
        uint32_t base = smBase + (uint32_t)(st * SP) * 2;
        cpa16(base + (uint32_t)soffA1 * 2, gA1 + k0);
        cpa16(base + (uint32_t)soffA2 * 2, gA2 + k0);
        cpa16(base + (uint32_t)(offB + soffB) * 2, gB + k0);
    };

    load_stage(0, 0);
    cpa_commit();

    for (int it = 0; it < ntiles; it++) {
        if (it + 1 < ntiles) { load_stage((it + 1) & 1, (it + 1) << 5); cpa_commit(); cpa_wait1(); }
        else cpa_wait0();
        __syncthreads();

        const int st = it & 1;
        const uint32_t aB = smBase + (uint32_t)(st * SP) * 2;
        const __half* sB = smh + st * SP + offB;

#pragma unroll
        for (int ks = 0; ks < 32; ks += 16) {
            uint32_t af[4][4];
#pragma unroll
            for (int mi = 0; mi < 4; mi++) {
                uint32_t off = (uint32_t)(((arow + mi * 16) * GS + ks + acol) * 2);
                ldsm_x4(af[mi], aB + off);
            }
#pragma unroll
            for (int ni = 0; ni < 4; ni++) {
                int bidx = (wn * 32 + ni * 8 + bg) * GS + ks + bt;
                uint32_t b0 = *(const uint32_t*)&sB[bidx];
                uint32_t b1 = *(const uint32_t*)&sB[bidx + 8];
#pragma unroll
                for (int mi = 0; mi < 4; mi++)
                    mma_fp16(acc[mi][ni], af[mi], b0, b1);
            }
        }
        __syncthreads();
    }

    const int gr = lane >> 2;
    const int gc = (lane & 3) << 1;
#pragma unroll
    for (int mi = 0; mi < 4; mi++) {
        size_t r0 = bm + wm * 64 + mi * 16 + gr;
#pragma unroll
        for (int ni = 0; ni < 4; ni++) {
            size_t c0 = bn + wn * 32 + ni * 8 + gc;
            float bv0 = bias ? bias[c0] : 0.f;
            float bv1 = bias ? bias[c0 + 1] : 0.f;
#pragma unroll
            for (int half = 0; half < 2; half++) {
                size_t row = r0 + half * 8;
                float v0 = acc[mi][ni][half * 2 + 0] + bv0;
                float v1 = acc[mi][ni][half * 2 + 1] + bv1;
                size_t o = row * ldc + c0;
                if (resid) {
                    float2 rv = *(const float2*)(resid + o);
                    v0 += rv.x; v1 += rv.y;
                }
                if (act) { v0 = gelu_exact(v0); v1 = gelu_exact(v1); }
                if (Cf)  *(float2*)(Cf + o) = make_float2(v0, v1);
                if (Chf) *(__half2*)(Chf + o) = __floats2half2_rn(v0, v1);
            }
        }
    }
}

// ---------------- dedicated scores kernel (persistent A) ----------------
#define SGS 72
#define SAPL (256*SGS)
#define SBPL (128*SGS)
__global__ void __launch_bounds__(512, 1) scores_kernel(
    const __nv_bfloat16* __restrict__ qh, const __nv_bfloat16* __restrict__ ql,
    const __nv_bfloat16* __restrict__ kh, const __nv_bfloat16* __restrict__ kl,
    float* __restrict__ S)
{
    extern __shared__ __nv_bfloat16 sm[];
    const int offAl = SAPL;
    const int offB  = 2 * SAPL;
    const int BSTG  = 2 * SBPL;

    const int tid = threadIdx.x, lane = tid & 31, warp = tid >> 5;
    const int wm = warp >> 2, wn = warp & 3;
    const int z = blockIdx.z, b = z / NH, h = z % NH;
    const size_t bm = (size_t)blockIdx.y * 256;
    const __nv_bfloat16* Ah = qh + (size_t)b * QQL * DDIM + h * HDIM;
    const __nv_bfloat16* Al = ql + (size_t)b * QQL * DDIM + h * HDIM;
    const __nv_bfloat16* Bh = kh + (size_t)b * KKL * DDIM + h * HDIM;
    const __nv_bfloat16* Bl = kl + (size_t)b * KKL * DDIM + h * HDIM;
    float* C = S + ((size_t)(b * NH + h) * QQL + bm) * KKL;

    const uint32_t smBase = smem_u32(sm);

#pragma unroll
    for (int i = 0; i < 4; i++) {
        int c = tid + 512 * i;
        int row = c >> 3;
        int seg = (c & 7) * 8;
        uint32_t d = smBase + (uint32_t)(row * SGS + seg) * 2;
        cpa16(d, Ah + (bm + row) * (size_t)DDIM + seg);
        cpa16(d + (uint32_t)offAl * 2, Al + (bm + row) * (size_t)DDIM + seg);
    }
    auto load_B = [&](int st, int kt) {
        uint32_t base = smBase + (uint32_t)(offB + st * BSTG) * 2;
#pragma unroll
        for (int i = 0; i < 2; i++) {
            int c = tid + 512 * i;
            int row = c >> 3;
            int seg = (c & 7) * 8;
            uint32_t d = base + (uint32_t)(row * SGS + seg) * 2;
            cpa16(d, Bh + (size_t)(kt * 128 + row) * DDIM + seg);
            cpa16(d + (uint32_t)SBPL * 2, Bl + (size_t)(kt * 128 + row) * DDIM + seg);
        }
    };
    load_B(0, 0);
    cpa_commit();

    const int arow = wm * 64 + (lane & 15);
    const int acol = (lane >> 4) << 3;
    const int bg = lane >> 2, bt = (lane & 3) << 1;
    const uint32_t aH = smBase;
    const uint32_t aL = smBase + (uint32_t)offAl * 2;
    const int gr = lane >> 2;
    const int gc = (lane & 3) << 1;

    for (int kt = 0; kt < 8; kt++) {
        if (kt + 1 < 8) { load_B((kt + 1) & 1, kt + 1); cpa_commit(); cpa_wait1(); }
        else cpa_wait0();
        __syncthreads();
        const __nv_bfloat16* sBh = sm + offB + (kt & 1) * BSTG;
        const __nv_bfloat16* sBl = sBh + SBPL;

        float acc[4][4][4];
#pragma unroll
        for (int i = 0; i < 4; i++)
#pragma unroll
            for (int j = 0; j < 4; j++)
#pragma unroll
                for (int t = 0; t < 4; t++) acc[i][j][t] = 0.f;

#pragma unroll
        for (int ks = 0; ks < 64; ks += 16) {
            uint32_t afh[4][4], afl[4][4];
#pragma unroll
            for (int mi = 0; mi < 4; mi++) {
                uint32_t off = (uint32_t)(((arow + mi * 16) * SGS + ks + acol) * 2);
                ldsm_x4(afh[mi], aH + off);
                ldsm_x4(afl[mi], aL + off);
            }
#pragma unroll
            for (int ni = 0; ni < 4; ni++) {
                int bidx = (wn * 32 + ni * 8 + bg) * SGS + ks + bt;
                uint32_t bh0 = *(const uint32_t*)&sBh[bidx];
                uint32_t bh1 = *(const uint32_t*)&sBh[bidx + 8];
                uint32_t bl0 = *(const uint32_t*)&sBl[bidx];
                uint32_t bl1 = *(const uint32_t*)&sBl[bidx + 8];
#pragma unroll
                for (int mi = 0; mi < 4; mi++) {
                    mma_bf16(acc[mi][ni], afh[mi], bh0, bh1);
                    mma_bf16(acc[mi][ni], afl[mi], bh0, bh1);
                    mma_bf16(acc[mi][ni], afh[mi], bl0, bl1);
                }
            }
        }

#pragma unroll
        for (int mi = 0; mi < 4; mi++) {
            size_t r0 = wm * 64 + mi * 16 + gr;
#pragma unroll
            for (int ni = 0; ni < 4; ni++) {
                size_t c0 = (size_t)kt * 128 + wn * 32 + ni * 8 + gc;
#pragma unroll
                for (int half = 0; half < 2; half++) {
                    size_t row = r0 + half * 8;
                    *(float2*)(C + row * KKL + c0) = make_float2(
                        acc[mi][ni][half * 2 + 0] * 0.125f,
                        acc[mi][ni][half * 2 + 1] * 0.125f);
                }
            }
        }
        __syncthreads();
    }
}

// ---------------- transpose V (fp32 -> bf16, [b,k,c] -> [b,c,k]) ----------------
__global__ void __launch_bounds__(256) transpose_split_kernel(
    const float* __restrict__ v, __nv_bfloat16* __restrict__ th)
{
    __shared__ float tile[32][33];
    int tx = threadIdx.x, ty = threadIdx.y;
    int c0 = blockIdx.x * 32;
    int r0 = blockIdx.y * 32;
#pragma unroll
    for (int i = 0; i < 4; i++)
        tile[ty + i * 8][tx] = v[(size_t)(r0 + ty + i * 8) * DDIM + c0 + tx];
    __syncthreads();
    int b = r0 >> 10;
    int kk0 = r0 & 1023;
#pragma unroll
    for (int i = 0; i < 4; i++) {
        float val = tile[tx][ty + i * 8];
        size_t o = ((size_t)(b << 10) + c0 + ty + i * 8) * 1024 + kk0 + tx;
        th[o] = __float2bfloat16_rn(val);
    }
}

// ---------------- fused masked softmax + head mean (2 heads / iter) ----------------
__global__ void __launch_bounds__(256) softmax_mean_kernel(
    const float* __restrict__ S, const void* __restrict__ mask,
    __nv_bfloat16* __restrict__ ah, float* __restrict__ mout)
{
    const int bq = blockIdx.x;
    const int b = bq >> 10, q = bq & 1023;
    const int t = threadIdx.x;
    const int k0 = t * 4;
    const int flag = g_mask_flag;
    const int lane = t & 31, w = t >> 5;

    bool mk[4];
#pragma unroll
    for (int i = 0; i < 4; i++) mk[i] = mask_valid(mask, b * KKL + k0 + i, flag);

    float macc[4] = {0.f, 0.f, 0.f, 0.f};
    __shared__ float red[16];
    const float NEG = -__int_as_float(0x7f800000);

    for (int h = 0; h < NH; h += 2) {
        const float* ra = S + (((size_t)(b * NH + h)) * QQL + q) * KKL;
        const float* rb = ra + (size_t)QQL * KKL;
        float4 a4 = *(const float4*)(ra + k0);
        float4 b4 = *(const float4*)(rb + k0);
        float va[4] = {a4.x, a4.y, a4.z, a4.w};
        float vb[4] = {b4.x, b4.y, b4.z, b4.w};
#pragma unroll
        for (int i = 0; i < 4; i++) if (!mk[i]) { va[i] = NEG; vb[i] = NEG; }

        float mxa = fmaxf(fmaxf(va[0], va[1]), fmaxf(va[2], va[3]));
        float mxb = fmaxf(fmaxf(vb[0], vb[1]), fmaxf(vb[2], vb[3]));
#pragma unroll
        for (int o = 16; o; o >>= 1) {
            mxa = fmaxf(mxa, __shfl_xor_sync(0xffffffffu, mxa, o));
            mxb = fmaxf(mxb, __shfl_xor_sync(0xffffffffu, mxb, o));
        }
        if (lane == 0) { red[w] = mxa; red[8 + w] = mxb; }
        __syncthreads();
        mxa = red[0]; mxb = red[8];
#pragma unroll
        for (int jj = 1; jj < 8; jj++) { mxa = fmaxf(mxa, red[jj]); mxb = fmaxf(mxb, red[8 + jj]); }
        __syncthreads();

        float sa = 0.f, sb = 0.f;
#pragma unroll
        for (int i = 0; i < 4; i++) {
            va[i] = expf(va[i] - mxa); sa += va[i];
            vb[i] = expf(vb[i] - mxb); sb += vb[i];
        }
#pragma unroll
        for (int o = 16; o; o >>= 1) {
            sa += __shfl_xor_sync(0xffffffffu, sa, o);
            sb += __shfl_xor_sync(0xffffffffu, sb, o);
        }
        if (lane == 0) { red[w] = sa; red[8 + w] = sb; }
        __syncthreads();
        float ta = red[0], tb = red[8];
#pragma unroll
        for (int jj = 1; jj < 8; jj++) { ta += red[jj]; tb += red[8 + jj]; }
        __syncthreads();
        float ia = 1.0f / ta, ib = 1.0f / tb;

        float pa0 = va[0] * ia, pa1 = va[1] * ia, pa2 = va[2] * ia, pa3 = va[3] * ia;
        float pb0 = vb[0] * ib, pb1 = vb[1] * ib, pb2 = vb[2] * ib, pb3 = vb[3] * ib;
        macc[0] += pa0 + pb0; macc[1] += pa1 + pb1;
        macc[2] += pa2 + pb2; macc[3] += pa3 + pb3;
        __nv_bfloat162* da = (__nv_bfloat162*)(ah + (((size_t)(b * NH + h)) * QQL + q) * KKL + k0);
        da[0] = __nv_bfloat162(__float2bfloat16_rn(pa0), __float2bfloat16_rn(pa1));
        da[1] = __nv_bfloat162(__float2bfloat16_rn(pa2), __float2bfloat16_rn(pa3));
        __nv_bfloat162* db = (__nv_bfloat162*)(ah + (((size_t)(b * NH + h + 1)) * QQL + q) * KKL + k0);
        db[0] = __nv_bfloat162(__float2bfloat16_rn(pb0), __float2bfloat16_rn(pb1));
        db[1] = __nv_bfloat162(__float2bfloat16_rn(pb2), __float2bfloat16_rn(pb3));
    }

    float4 mo;
    mo.x = macc[0] * (1.0f / NH); mo.y = macc[1] * (1.0f / NH);
    mo.z = macc[2] * (1.0f / NH); mo.w = macc[3] * (1.0f / NH);
    *(float4*)(mout + ((size_t)bq) * KKL + k0) = mo;
}

// ---------------- AV (mma.sync, 1-pass bf16, cp.async 2-stage) ----------------
#define AVP (128*GS)
#define BVP (64*GS)
__global__ void __launch_bounds__(256, 2) av_kernel(
    const __nv_bfloat16* __restrict__ attn, const __nv_bfloat16* __restrict__ vt,
    __nv_bfloat16* __restrict__ Ch)
{
    __shared__ __nv_bfloat16 sm[2 * (AVP + BVP)];
    const int tid = threadIdx.x;
    const int lane = tid & 31;
    const int warp = tid >> 5;
    const int wm = warp >> 2, wn = warp & 3;
    const int z = blockIdx.z;
    const int b = z / NH, h = z % NH;
    const size_t bm = (size_t)blockIdx.y * 128;

    const __nv_bfloat16* A = attn + (size_t)z * QQL * KKL;
    const __nv_bfloat16* W = vt + ((size_t)b * 1024 + h * 64) * 1024;
    const size_t Coff = (size_t)b * QQL * DDIM + h * HDIM;

    const int lrow = tid >> 1;
    const int lseg = (tid & 1) * 16;
    const __nv_bfloat16* gA = A + (bm + lrow) * (size_t)KKL + lseg;
    const int soffA = lrow * GS + lseg;
    const int brow = tid >> 2;
    const int bseg = (tid & 3) * 8;
    const __nv_bfloat16* gB = W + (size_t)brow * 1024 + bseg;
    const int soffB = brow * GS + bseg;

    const uint32_t smBase = smem_u32(sm);
    const int arow = wm * 64 + (lane & 15);
    const int acol = (lane >> 4) << 3;
    const int bg = lane >> 2;
    const int bt = (lane & 3) << 1;
    const int SP2 = AVP + BVP;

    float acc[4][2][4];
#pragma unroll
    for (int i = 0; i < 4; i++)
#pragma unroll
        for (int jq = 0; jq < 2; jq++)
#pragma unroll
            for (int t = 0; t < 4; t++) acc[i][jq][t] = 0.f;

    auto load_stage = [&](int st, int k0) {
        uint32_t d = smBase + (uint32_t)(st * SP2 + soffA) * 2;
        cpa16(d,      gA + k0);
        cpa16(d + 16, gA + k0 + 8);
        uint32_t db = smBase + (uint32_t)(st * SP2 + AVP + soffB) * 2;
        cpa16(db, gB + k0);
    };

    load_stage(0, 0);
    cpa_commit();

    for (int it = 0; it < 32; it++) {
        if (it + 1 < 32) { load_stage((it + 1) & 1, (it + 1) << 5); cpa_commit(); cpa_wait1(); }
        else cpa_wait0();
        __syncthreads();

        const int st = it & 1;
        const uint32_t aBase = smBase + (uint32_t)(st * SP2) * 2;
        const __nv_bfloat16* sB = sm + st * SP2 + AVP;

#pragma unroll
        for (int ks = 0; ks < 32; ks += 16) {
            uint32_t af[4][4];
#pragma unroll
            for (int mi = 0; mi < 4; mi++) {
                uint32_t off = (uint32_t)(((arow + mi * 16) * GS + ks + acol) * 2);
                ldsm_x4(af[mi], aBase + off);
            }
#pragma unroll
            for (int ni = 0; ni < 2; ni++) {
                int bidx = (wn * 16 + ni * 8 + bg) * GS + ks + bt;
                uint32_t b0 = *(const uint32_t*)&sB[bidx];
                uint32_t b1 = *(const uint32_t*)&sB[bidx + 8];
#pragma unroll
                for (int mi = 0; mi < 4; mi++)
                    mma_bf16(acc[mi][ni], af[mi], b0, b1);
            }
        }
        __syncthreads();
    }

    const int gr = lane >> 2;
    const int gc = (lane & 3) << 1;
#pragma unroll
    for (int mi = 0; mi < 4; mi++) {
        size_t r0 = bm + wm * 64 + mi * 16 + gr;
#pragma unroll
        for (int ni = 0; ni < 2; ni++) {
            int c0 = wn * 16 + ni * 8 + gc;
#pragma unroll
            for (int half = 0; half < 2; half++) {
                size_t row = r0 + half * 8;
                size_t o = Coff + row * DDIM + c0;
                *(__nv_bfloat162*)(Ch + o) = __nv_bfloat162(
                    __float2bfloat16_rn(acc[mi][ni][half * 2 + 0]),
                    __float2bfloat16_rn(acc[mi][ni][half * 2 + 1]));
            }
        }
    }
}

// ---------------- launch ----------------
extern "C" void kernel_launch(void* const* d_in, const int* in_sizes, int n_in,
                              void* d_out, int out_size)
{
    const float* query      = (const float*)d_in[0];
    const float* key_value  = (const float*)d_in[1];
    const void*  kpm        = d_in[2];
    const float* ln_q_w     = (const float*)d_in[3];
    const float* ln_q_b     = (const float*)d_in[4];
    const float* ln_kv_w    = (const float*)d_in[5];
    const float* ln_kv_b    = (const float*)d_in[6];
    const float* ln_f_w     = (const float*)d_in[7];
    const float* ln_f_b     = (const float*)d_in[8];
    const float* in_proj_w  = (const float*)d_in[9];
    const float* in_proj_b  = (const float*)d_in[10];
    const float* out_proj_w = (const float*)d_in[11];
    const float* out_proj_b = (const float*)d_in[12];
    const float* ffn_w1     = (const float*)d_in[13];
    const float* ffn_b1     = (const float*)d_in[14];
    const float* ffn_w2     = (const float*)d_in[15];
    const float* ffn_b2     = (const float*)d_in[16];

    float* out_x    = (float*)d_out;
    float* out_attn = out_x + (size_t)BB * QQL * DDIM;

    __nv_bfloat16 *xnh, *xnl, *qkph, *qkpl, *aoh, *wh, *wl, *vth, *ath;
    __half *lnf16, *h16, *w16;
    float *vp, *sc, *xb;
    cudaGetSymbolAddress((void**)&xnh,  g_xn_h);  cudaGetSymbolAddress((void**)&xnl,  g_xn_l);
    cudaGetSymbolAddress((void**)&qkph, g_qkp_h); cudaGetSymbolAddress((void**)&qkpl, g_qkp_l);
    cudaGetSymbolAddress((void**)&lnf16, g_lnf16);
    cudaGetSymbolAddress((void**)&aoh,  g_ao_h);
    cudaGetSymbolAddress((void**)&h16,  g_h16);
    cudaGetSymbolAddress((void**)&wh,   g_w_h);   cudaGetSymbolAddress((void**)&wl,   g_w_l);
    cudaGetSymbolAddress((void**)&w16,  g_w16);
    cudaGetSymbolAddress((void**)&vth,  g_vt_h);
    cudaGetSymbolAddress((void**)&ath,  g_attn_h);
    cudaGetSymbolAddress((void**)&vp,   g_v);
    cudaGetSymbolAddress((void**)&sc,   g_scores);
    cudaGetSymbolAddress((void**)&xb,   g_x);

    const size_t M1 = (size_t)1024 * 1024;
    const size_t MD = (size_t)MROWS * DDIM;
    const size_t OFF_OUT  = 3 * M1;
    const size_t OFF_W16_FFN2 = 4 * M1;

    const int SM3 = 2 * (2 * APLANE + 2 * BPLANE) * 2;   // 122880 B
    const int SM1 = 2 * (APLANE + BPLANE) * 2;           //  61440 B
    const int SMS = (2 * SAPL + 2 * 2 * SBPL) * 2;       // 147456 B
    cudaFuncSetAttribute(gemm3_kernel,     cudaFuncAttributeMaxDynamicSharedMemorySize, SM3);
    cudaFuncSetAttribute(gemm_fp16_kernel, cudaFuncAttributeMaxDynamicSharedMemorySize, SM1);
    cudaFuncSetAttribute(scores_kernel,    cudaFuncAttributeMaxDynamicSharedMemorySize, SMS);

    detect_mask_kernel<<<1, 256>>>((const unsigned char*)kpm);

    // weight preprocessing: in_proj hi/lo (q,k 3-pass + v 1-pass use hi), out_proj hi,
    // ffn1/ffn2 -> fp16 single plane
    split_kernel<<<(unsigned)(3 * M1 / 1024), 256>>>(in_proj_w, wh, wl, 3 * M1);
    split_kernel<<<(unsigned)(1 * M1 / 1024), 256>>>(out_proj_w, wh + OFF_OUT, wl + OFF_OUT, 1 * M1);
    tofp16_kernel<<<(unsigned)(4 * M1 / 1024), 256>>>(ffn_w1, w16,               4 * M1);
    tofp16_kernel<<<(unsigned)(4 * M1 / 1024), 256>>>(ffn_w2, w16 + OFF_W16_FFN2, 4 * M1);

    ln_split_kernel<<<MROWS, 256>>>(query,     ln_q_w,  ln_q_b,  xnh,      xnl);
    ln_split_kernel<<<MROWS, 256>>>(key_value, ln_kv_w, ln_kv_b, xnh + MD, xnl + MD);

    // merged q+k proj (3-pass, z=2)
    dim3 gqk(DDIM / 128, MROWS / 256, 2);
    gemm3_kernel<<<gqk, 512, SM3>>>(xnh, xnl, DDIM, 0, (long)MD,
                                    wh, wl, DDIM, 0, (long)M1,
                                    in_proj_b, DDIM, nullptr,
                                    nullptr, qkph, qkpl, DDIM, 0, (long)MD,
                                    DDIM, 1.f, 0, 1);
    // v proj (1-pass -> fp32)
    dim3 g1024(DDIM / 128, MROWS / 256, 1);
    gemm3_kernel<<<g1024, 512, SM1>>>(xnh + MD, xnh + MD, DDIM, 0, 0,
                                      wh + 2 * M1, wh + 2 * M1, DDIM, 0, 0,
                                      in_proj_b + 2 * DDIM, 0, nullptr,
                                      vp, nullptr, nullptr, DDIM, 0, 0,
                                      DDIM, 1.f, 0, 0);
    transpose_split_kernel<<<dim3(DDIM / 32, MROWS / 32), dim3(32, 8)>>>(vp, vth);

    // scores (persistent-A, 3-pass)
    dim3 gsc(1, QQL / 256, BB * NH);
    scores_kernel<<<gsc, 512, SMS>>>(qkph, qkpl, qkph + MD, qkpl + MD, sc);

    softmax_mean_kernel<<<BB * QQL, 256>>>(sc, kpm, ath, out_attn);

    dim3 gav(1, QQL / 128, BB * NH);
    av_kernel<<<gav, 256>>>(ath, vth, aoh);

    // out_proj + residual (1-pass -> fp32)
    gemm3_kernel<<<g1024, 512, SM1>>>(aoh, aoh, DDIM, 0, 0,
                                      wh + OFF_OUT, wh + OFF_OUT, DDIM, 0, 0,
                                      out_proj_b, 0, query,
                                      xb, nullptr, nullptr, DDIM, 0, 0,
                                      DDIM, 1.f, 0, 0);

    // final LN -> fp16
    ln_fp16_kernel<<<MROWS, 256>>>(xb, ln_f_w, ln_f_b, lnf16);

    // ffn1 (fp16 1-pass, gelu -> fp16)
    dim3 gff1(FFD / 128, MROWS / 256, 1);
    gemm_fp16_kernel<<<gff1, 512, SM1>>>(lnf16, DDIM, w16, DDIM,
                                         ffn_b1, nullptr,
                                         nullptr, h16, FFD, DDIM, 1);
    // ffn2 (fp16 1-pass, residual -> fp32)
    gemm_fp16_kernel<<<g1024, 512, SM1>>>(h16, FFD, w16 + OFF_W16_FFN2, FFD,
                                          ffn_b2, xb,
                                          out_x, nullptr, DDIM, FFD, 0);
}